// round 8
// baseline (speedup 1.0000x reference)
#include <cuda_runtime.h>
#include <cstdint>

// ---------------------------------------------------------------------------
// KAN 2-layer fused, round 8: vectorized slot producers + 64x64 tiles,
// 3 CTAs/SM.
//   D[o,b] = sum_{i,g} W[o,i,g] * f_g(x[b,i])
//   f = {basis_0..7(x), silu(x)},  W = {ssp*coef_0..7, sb}
//   Chunk K layout: kk = g*8 + ii  (9 planes of 8 inputs, K=72/chunk)
//   K2 CTA: M=64 (o) x N=64 (b) x K=432; grid (4 o x 2 b x 64 splits)=512.
// ---------------------------------------------------------------------------

#define B_     128
#define IN_    3072
#define H_     256
#define OUT_   10
#define KSPLIT 64
#define IPC    48          // inputs per CTA
#define NCH    6           // chunks of 8 inputs
#define NKS    9           // feature planes per chunk

__device__ float g_Y1p[KSPLIT * B_ * H_];    // layer-1 partials [split][b][o]
__device__ float g_Y1[B_ * H_];              // reduced layer-1 pre-activation

// ---- smem: A/B tiles 18KB each, double buffered = 72KB -> 3 CTAs/SM -------
#define SM_A0    0
#define SM_A1    18432
#define SM_B0    36864
#define SM_B1    55296
#define SMEM_TOTAL 73728
#define SPW      68        // writeout transpose pitch

// ---- helpers ---------------------------------------------------------------
__device__ __forceinline__ uint32_t tf32r(float x) {
    uint32_t r;
    asm("cvt.rna.tf32.f32 %0, %1;" : "=r"(r) : "f"(x));
    return r;
}
__device__ __forceinline__ float tf32f(float x) { return __uint_as_float(tf32r(x)); }
__device__ __forceinline__ void mma8(float d[4], const uint32_t a[4], const uint32_t b[2]) {
    asm volatile("mma.sync.aligned.m16n8k8.row.col.f32.tf32.tf32.f32 "
        "{%0,%1,%2,%3}, {%4,%5,%6,%7}, {%8,%9}, {%0,%1,%2,%3};"
        : "+f"(d[0]), "+f"(d[1]), "+f"(d[2]), "+f"(d[3])
        : "r"(a[0]), "r"(a[1]), "r"(a[2]), "r"(a[3]), "r"(b[0]), "r"(b[1]));
}
__device__ __forceinline__ float silu_f(float x) { return x / (1.0f + __expf(-x)); }
__device__ __forceinline__ float selu_f(float x) {
    const float scale = 1.0507009873554805f;
    const float alpha = 1.6732632423543772f;
    return x > 0.0f ? scale * x : scale * alpha * expm1f(x);
}

// Closed-form cubic B-spline on uniform extended grid t_j = -2.2 + 0.4 j
// (validated rounds 4-7 vs Cox-de-Boor).
struct Bsp { float w0, w1, w2, w3; int m; };
__device__ __forceinline__ Bsp bspline4(float x) {
    Bsp r;
    float tpos = (x + 2.2f) * 2.5f;
    float mf = floorf(tpos);
    r.m = (int)mf;
    float u = tpos - mf;
    float u2 = u * u, u3 = u2 * u, om = 1.0f - u;
    bool valid = (x >= -2.2f) && (r.m <= 10);
    float s = valid ? (1.0f / 6.0f) : 0.0f;
    r.w0 = om * om * om * s;
    r.w1 = (3.0f * u3 - 6.0f * u2 + 4.0f) * s;
    r.w2 = (-3.0f * u3 + 3.0f * u2 + 3.0f * u + 1.0f) * s;
    r.w3 = u3 * s;
    return r;
}
__device__ __forceinline__ float bsp_at(const Bsp& r, int g) {
    int d = r.m - g;
    float v = 0.0f;
    v = (d == 3) ? r.w0 : v;
    v = (d == 2) ? r.w1 : v;
    v = (d == 1) ? r.w2 : v;
    v = (d == 0) ? r.w3 : v;
    return v;
}

// ---------------------------------------------------------------------------
// K2: layer-1 GEMM on mma.sync, slot-vectorized producers.
//   A_s[g][mt4][lane32]{float4}: 16B slot = edges {r,r+8}x{ii,ii+4}
//   B_s[g][nt8][lane32]{float2}: 8B slot  = edges b x {ii,ii+4}
// ---------------------------------------------------------------------------
__global__ void __launch_bounds__(256, 3) k2_mma(const float* __restrict__ x,
                                                const float* __restrict__ coef1,
                                                const float* __restrict__ sb1,
                                                const float* __restrict__ ssp1) {
    extern __shared__ __align__(16) char smem[];

    const int tid  = threadIdx.x;
    const int lane = tid & 31;
    const int wid  = tid >> 5;
    const int wm   = wid >> 2;          // 0..1 : 32 o per warp-row
    const int wn   = wid & 3;           // 0..3 : 16 b per warp-col
    const int o0   = (blockIdx.x >> 1) * 64;
    const int b0   = (blockIdx.x & 1) * 64;
    const int split = blockIdx.y;
    const int i0   = split * IPC;

    float acc[2][2][4];
#pragma unroll
    for (int mi = 0; mi < 2; mi++)
#pragma unroll
        for (int ni = 0; ni < 2; ni++)
#pragma unroll
            for (int w = 0; w < 4; w++) acc[mi][ni][w] = 0.0f;

    // ---- A slot assignment: slot = tid>>1 (128 slots), half = tid&1 ----
    const int a_slot = tid >> 1;
    const int a_half = tid & 1;            // 0: c0 planes 0-3 + sb plane 8; 1: c1 planes 4-7
    const int a_mt   = a_slot >> 5;
    const int a_ln   = a_slot & 31;
    const int a_r8   = a_ln >> 2;
    const int a_ic   = a_ln & 3;
    const uint32_t a_base = (a_mt * 32 + a_ln) * 4;     // + g*512 (u32)

    // ---- B slot assignment: one slot per thread (256 slots) ----
    const int b_nt   = tid >> 5;
    const int b_ln   = tid & 31;
    const int b_row  = b0 + b_nt * 8 + (b_ln >> 2);
    const int b_ic   = b_ln & 3;
    const uint32_t b_base = (b_nt * 32 + b_ln) * 2;     // + g*512 (u32)

    // ---- staging ----
    float4 pc[4];
    float  psp[4], psb[4];
    float  px0, px1;

    auto ldgA = [&](int ib) {
#pragma unroll
        for (int j = 0; j < 4; j++) {
            int o = o0 + a_mt * 16 + a_r8 + 8 * (j & 1);
            int i = ib + a_ic + 4 * (j >> 1);
            int e = o * IN_ + i;
            pc[j]  = ((const float4*)coef1)[e * 2 + a_half];
            psp[j] = ssp1[e];
            if (a_half == 0) psb[j] = sb1[e];
        }
    };
    auto ldgB = [&](int ib) {
        px0 = x[b_row * IN_ + ib + b_ic];
        px1 = x[b_row * IN_ + ib + b_ic + 4];
    };
    auto stsA = [&](uint32_t offA) {
        uint32_t* As = (uint32_t*)(smem + offA);
        float v0[4], v1[4], v2[4], v3[4];
#pragma unroll
        for (int j = 0; j < 4; j++) {
            v0[j] = tf32f(psp[j] * pc[j].x);
            v1[j] = tf32f(psp[j] * pc[j].y);
            v2[j] = tf32f(psp[j] * pc[j].z);
            v3[j] = tf32f(psp[j] * pc[j].w);
        }
        int gbase = a_half * 4;            // planes 0-3 or 4-7
        *(float4*)&As[(gbase + 0) * 512 + a_base] = make_float4(v0[0], v0[1], v0[2], v0[3]);
        *(float4*)&As[(gbase + 1) * 512 + a_base] = make_float4(v1[0], v1[1], v1[2], v1[3]);
        *(float4*)&As[(gbase + 2) * 512 + a_base] = make_float4(v2[0], v2[1], v2[2], v2[3]);
        *(float4*)&As[(gbase + 3) * 512 + a_base] = make_float4(v3[0], v3[1], v3[2], v3[3]);
        if (a_half == 0) {
            *(float4*)&As[8 * 512 + a_base] =
                make_float4(tf32f(psb[0]), tf32f(psb[1]), tf32f(psb[2]), tf32f(psb[3]));
        }
    };
    auto prodB = [&](uint32_t offB) {
        uint32_t* Bs = (uint32_t*)(smem + offB);
#pragma unroll
        for (int g = 0; g < 8; g++)
            *(float2*)&Bs[g * 512 + b_base] = make_float2(0.0f, 0.0f);
        Bsp bs0 = bspline4(px0);
        Bsp bs1 = bspline4(px1);
        float w0[4] = { bs0.w0, bs0.w1, bs0.w2, bs0.w3 };
        float w1[4] = { bs1.w0, bs1.w1, bs1.w2, bs1.w3 };
#pragma unroll
        for (int j = 0; j < 4; j++) {
            int g0 = bs0.m - 3 + j;
            if (g0 >= 0 && g0 <= 7) Bs[g0 * 512 + b_base]     = tf32r(w0[j]);
            int g1 = bs1.m - 3 + j;
            if (g1 >= 0 && g1 <= 7) Bs[g1 * 512 + b_base + 1] = tf32r(w1[j]);
        }
        *(float2*)&Bs[8 * 512 + b_base] =
            make_float2(tf32f(silu_f(px0)), tf32f(silu_f(px1)));
    };
    auto consume = [&](uint32_t offA, uint32_t offB) {
        const float4* As = (const float4*)(smem + offA);
        const float2* Bs = (const float2*)(smem + offB);
#pragma unroll
        for (int ks = 0; ks < NKS; ks++) {
            uint32_t af[2][4], bf[2][2];
#pragma unroll
            for (int mi = 0; mi < 2; mi++) {
                float4 v = As[(ks * 4 + wm * 2 + mi) * 32 + lane];
                af[mi][0] = __float_as_uint(v.x); af[mi][1] = __float_as_uint(v.y);
                af[mi][2] = __float_as_uint(v.z); af[mi][3] = __float_as_uint(v.w);
            }
#pragma unroll
            for (int ni = 0; ni < 2; ni++) {
                float2 v = Bs[(ks * 8 + wn * 2 + ni) * 32 + lane];
                bf[ni][0] = __float_as_uint(v.x); bf[ni][1] = __float_as_uint(v.y);
            }
#pragma unroll
            for (int mi = 0; mi < 2; mi++)
#pragma unroll
                for (int ni = 0; ni < 2; ni++) mma8(acc[mi][ni], af[mi], bf[ni]);
        }
    };

    // --- pipeline: ldg(t+1); consume(t); sts(t+1); sync ---
    ldgA(i0); ldgB(i0);
    stsA(SM_A0); prodB(SM_B0);
    __syncthreads();

    for (int t = 0; t < NCH; t++) {
        const uint32_t offA = (t & 1) ? SM_A1 : SM_A0;
        const uint32_t offB = (t & 1) ? SM_B1 : SM_B0;
        const uint32_t nfA  = (t & 1) ? SM_A0 : SM_A1;
        const uint32_t nfB  = (t & 1) ? SM_B0 : SM_B1;
        if (t + 1 < NCH) { ldgA(i0 + (t + 1) * 8); ldgB(i0 + (t + 1) * 8); }
        consume(offA, offB);
        if (t + 1 < NCH) { stsA(nfA); prodB(nfB); }
        __syncthreads();
    }

    // --- writeout: transpose through smem, coalesced float4 partial stores ---
    {
        float* S = (float*)(smem + SM_A0);      // [64 b][pitch 68]
        const int r = lane >> 2, c = lane & 3;
#pragma unroll
        for (int mi = 0; mi < 2; mi++)
#pragma unroll
            for (int ni = 0; ni < 2; ni++)
#pragma unroll
                for (int w = 0; w < 4; w++) {
                    int o_l = (wm * 2 + mi) * 16 + r + 8 * (w >> 1);
                    int b_l = (wn * 2 + ni) * 8 + 2 * c + (w & 1);
                    S[b_l * SPW + o_l] = acc[mi][ni][w];
                }
        __syncthreads();
        float* Y = g_Y1p + split * (B_ * H_);
#pragma unroll
        for (int p = 0; p < 4; p++) {
            int idx = tid + 256 * p;
            int bb = idx >> 4, o4 = idx & 15;
            float4 v = *(float4*)&S[bb * SPW + o4 * 4];
            *(float4*)&Y[(b0 + bb) * H_ + o0 + o4 * 4] = v;
        }
    }
}

// ---------------------------------------------------------------------------
// K3a: split reduction, 256 CTAs (validated round 5).
// ---------------------------------------------------------------------------
__global__ void __launch_bounds__(256) k3a_reduce() {
    __shared__ float4 sred[8][32];
    const int t = threadIdx.x, c = blockIdx.x;
    const int lane = t & 31, w = t >> 5;
    const int out = c * 32 + lane;
    const int b = out >> 6, o4 = out & 63;

    const float4* P = (const float4*)g_Y1p;
    float4 acc = make_float4(0.f, 0.f, 0.f, 0.f);
#pragma unroll
    for (int k = 0; k < 8; k++) {
        int s = w * 8 + k;
        float4 v = P[(s * B_ + b) * (H_ / 4) + o4];
        acc.x += v.x; acc.y += v.y; acc.z += v.z; acc.w += v.w;
    }
    sred[w][lane] = acc;
    __syncthreads();
    if (t < 32) {
        float4 a = sred[0][t];
#pragma unroll
        for (int j = 1; j < 8; j++) {
            float4 v = sred[j][t];
            a.x += v.x; a.y += v.y; a.z += v.z; a.w += v.w;
        }
        ((float4*)g_Y1)[c * 32 + t] = a;
    }
}

// ---------------------------------------------------------------------------
// K3b: layer 2, shfl reduction (validated round 5).
// ---------------------------------------------------------------------------
__global__ void __launch_bounds__(256) k3b_layer2(const float* __restrict__ coef2,
                                                 const float* __restrict__ sb2,
                                                 const float* __restrict__ ssp2,
                                                 float* __restrict__ out) {
    const int b = blockIdx.x;
    const int t = threadIdx.x;
    const int lane = t & 31, w = t >> 5;

    float h = selu_f(g_Y1[b * H_ + t]);
    Bsp bs = bspline4(h);
    float f0 = silu_f(h);
    float fb[8];
#pragma unroll
    for (int g = 0; g < 8; g++) fb[g] = bsp_at(bs, g);

    __shared__ float red[OUT_ * 8];
    float val[OUT_];
#pragma unroll
    for (int o = 0; o < OUT_; o++) {
        int e = o * H_ + t;
        float4 c0 = ((const float4*)coef2)[e * 2];
        float4 c1 = ((const float4*)coef2)[e * 2 + 1];
        float sp = ssp2[e];
        float spline = fb[0] * c0.x + fb[1] * c0.y + fb[2] * c0.z + fb[3] * c0.w
                     + fb[4] * c1.x + fb[5] * c1.y + fb[6] * c1.z + fb[7] * c1.w;
        val[o] = sb2[e] * f0 + sp * spline;
    }
#pragma unroll
    for (int o = 0; o < OUT_; o++) {
#pragma unroll
        for (int off = 16; off > 0; off >>= 1)
            val[o] += __shfl_down_sync(0xFFFFFFFFu, val[o], off);
    }
    if (lane == 0) {
#pragma unroll
        for (int o = 0; o < OUT_; o++) red[o * 8 + w] = val[o];
    }
    __syncthreads();
    if (t < OUT_) {
        float s = 0.0f;
#pragma unroll
        for (int j = 0; j < 8; j++) s += red[t * 8 + j];
        out[b * OUT_ + t] = s;
    }
}

// ---------------------------------------------------------------------------
extern "C" void kernel_launch(void* const* d_in, const int* in_sizes, int n_in,
                              void* d_out, int out_size) {
    const float* x     = (const float*)d_in[0];
    const float* coef1 = (const float*)d_in[1];
    const float* sb1   = (const float*)d_in[2];
    const float* ssp1  = (const float*)d_in[3];
    const float* coef2 = (const float*)d_in[4];
    const float* sb2   = (const float*)d_in[5];
    const float* ssp2  = (const float*)d_in[6];
    float* out = (float*)d_out;

    cudaFuncSetAttribute(k2_mma, cudaFuncAttributeMaxDynamicSharedMemorySize, SMEM_TOTAL);
    k2_mma<<<dim3(8, KSPLIT), 256, SMEM_TOTAL>>>(x, coef1, sb1, ssp1);
    k3a_reduce<<<(B_ * H_) / (32 * 4), 256>>>();
    k3b_layer2<<<B_, 256>>>(coef2, sb2, ssp2, out);
}

// round 9
// speedup vs baseline: 1.4108x; 1.4108x over previous
#include <cuda_runtime.h>
#include <cstdint>

// ---------------------------------------------------------------------------
// KAN 2-layer fused, round 9: R5 config (128x128 tiles, best K2) with cheap
// producers: no tf32 cvt (raw fp32 -> RZ truncation in HMMA), vectorized
// conflict-free STS.128 A producer, slot-based conflict-free B producer.
//   D[o,b] = sum_{i,g} W[o,i,g] * f_g(x[b,i])
//   f = {basis_0..7(x), silu(x)},  W = {ssp*coef_0..7, sb}
//   Chunk K layout: kk = g*8 + ii  (9 planes of 8 inputs, K=72/chunk)
//   K2 CTA: M=128 (o) x N=128 (b) x K=432; grid (2 o-tiles x 64 splits).
// ---------------------------------------------------------------------------

#define B_     128
#define IN_    3072
#define H_     256
#define OUT_   10
#define KSPLIT 64
#define IPC    48          // inputs per CTA
#define NCH    6           // chunks of 8 inputs
#define NKS    9           // feature planes per chunk

__device__ float g_Y1p[KSPLIT * B_ * H_];    // layer-1 partials [split][b][o]
__device__ float g_Y1[B_ * H_];              // reduced layer-1 pre-activation

// ---- smem: A/B tiles 36KB each, double buffered = 144KB (1 CTA/SM) --------
#define SM_A0    0
#define SM_A1    36864
#define SM_B0    73728
#define SM_B1    110592
#define SMEM_TOTAL 147456
#define SP       132       // writeout transpose pitch

// ---- helpers ---------------------------------------------------------------
__device__ __forceinline__ void mma8(float d[4], const uint32_t a[4], const uint32_t b[2]) {
    asm volatile("mma.sync.aligned.m16n8k8.row.col.f32.tf32.tf32.f32 "
        "{%0,%1,%2,%3}, {%4,%5,%6,%7}, {%8,%9}, {%0,%1,%2,%3};"
        : "+f"(d[0]), "+f"(d[1]), "+f"(d[2]), "+f"(d[3])
        : "r"(a[0]), "r"(a[1]), "r"(a[2]), "r"(a[3]), "r"(b[0]), "r"(b[1]));
}
__device__ __forceinline__ float silu_f(float x) { return x / (1.0f + __expf(-x)); }
__device__ __forceinline__ float selu_f(float x) {
    const float scale = 1.0507009873554805f;
    const float alpha = 1.6732632423543772f;
    return x > 0.0f ? scale * x : scale * alpha * expm1f(x);
}

// Closed-form cubic B-spline on uniform extended grid t_j = -2.2 + 0.4 j
// (validated rounds 4-8 vs Cox-de-Boor).
struct Bsp { float w0, w1, w2, w3; int m; };
__device__ __forceinline__ Bsp bspline4(float x) {
    Bsp r;
    float tpos = (x + 2.2f) * 2.5f;
    float mf = floorf(tpos);
    r.m = (int)mf;
    float u = tpos - mf;
    float u2 = u * u, u3 = u2 * u, om = 1.0f - u;
    bool valid = (x >= -2.2f) && (r.m <= 10);
    float s = valid ? (1.0f / 6.0f) : 0.0f;
    r.w0 = om * om * om * s;
    r.w1 = (3.0f * u3 - 6.0f * u2 + 4.0f) * s;
    r.w2 = (-3.0f * u3 + 3.0f * u2 + 3.0f * u + 1.0f) * s;
    r.w3 = u3 * s;
    return r;
}
__device__ __forceinline__ float bsp_at(const Bsp& r, int g) {
    int d = r.m - g;
    float v = 0.0f;
    v = (d == 3) ? r.w0 : v;
    v = (d == 2) ? r.w1 : v;
    v = (d == 1) ? r.w2 : v;
    v = (d == 0) ? r.w3 : v;
    return v;
}

// ---------------------------------------------------------------------------
// K2: layer-1 GEMM on mma.sync.
//   A_s[g][mt8][lane32]{float4}: plane stride 1024 u32. Slot (mt,lane):
//     lane = r8*4 + ic; words w = q*2 + h -> edge (o = mt*16+r8+8h, i = ic+4q)
//   B_s[g][nt16][lane32]{float2}: plane stride 1024 u32. Slot (nt,lane):
//     lane = (b&7)*4 + ic; words: ii = ic (w0), ic+4 (w1); b = nt*8 + (lane>>2)
// ---------------------------------------------------------------------------
__global__ void __launch_bounds__(256, 1) k2_mma(const float* __restrict__ x,
                                                const float* __restrict__ coef1,
                                                const float* __restrict__ sb1,
                                                const float* __restrict__ ssp1) {
    extern __shared__ __align__(16) char smem[];

    const int tid  = threadIdx.x;
    const int lane = tid & 31;
    const int wid  = tid >> 5;
    const int wm   = wid >> 2;          // 0..1 : 64 o per warp-row
    const int wn   = wid & 3;           // 0..3 : 32 b per warp-col
    const int o0   = blockIdx.x * 128;
    const int split = blockIdx.y;
    const int i0   = split * IPC;

    float acc[4][4][4];
#pragma unroll
    for (int mi = 0; mi < 4; mi++)
#pragma unroll
        for (int ni = 0; ni < 4; ni++)
#pragma unroll
            for (int w = 0; w < 4; w++) acc[mi][ni][w] = 0.0f;

    // ---- A slot: thread = (mt, lane) ----
    const int a_mt = tid >> 5;            // 0..7
    const int a_ln = tid & 31;
    const int a_r8 = a_ln >> 2;           // 0..7
    const int a_ic = a_ln & 3;            // 0..3
    const uint32_t a_base = (uint32_t)(a_mt * 32 + a_ln) * 4;   // u32; +g*1024

    // ---- B slots: thread handles slots tid and tid+256 ----
    int      b_row[2], b_ic_[2];
    uint32_t b_base[2];
#pragma unroll
    for (int p = 0; p < 2; p++) {
        int s = tid + 256 * p;
        int nt = s >> 5, ln = s & 31;
        b_row[p]  = nt * 8 + (ln >> 2);
        b_ic_[p]  = ln & 3;
        b_base[p] = (uint32_t)(nt * 32 + ln) * 2;               // u32; +g*1024
    }

    // ---- staging registers ----
    float4 pc0[4], pc1[4];
    float  psp[4], psb[4];
    float  px[2][2];

    auto ldgA = [&](int ib) {
#pragma unroll
        for (int q = 0; q < 2; q++)
#pragma unroll
            for (int h = 0; h < 2; h++) {
                int j = q * 2 + h;                        // == fragment word
                int o = o0 + a_mt * 16 + a_r8 + 8 * h;
                int i = ib + a_ic + 4 * q;
                int e = o * IN_ + i;
                pc0[j] = ((const float4*)coef1)[e * 2];
                pc1[j] = ((const float4*)coef1)[e * 2 + 1];
                psp[j] = ssp1[e];
                psb[j] = sb1[e];
            }
    };
    auto ldgB = [&](int ib) {
#pragma unroll
        for (int p = 0; p < 2; p++) {
            px[p][0] = x[b_row[p] * IN_ + ib + b_ic_[p]];
            px[p][1] = x[b_row[p] * IN_ + ib + b_ic_[p] + 4];
        }
    };
    auto stsA = [&](uint32_t offA) {
        float* As = (float*)(smem + offA);
        // planes 0..3 from c0, 4..7 from c1, 8 from sb (raw fp32, no cvt)
        *(float4*)&As[0 * 1024 + a_base] = make_float4(psp[0]*pc0[0].x, psp[1]*pc0[1].x, psp[2]*pc0[2].x, psp[3]*pc0[3].x);
        *(float4*)&As[1 * 1024 + a_base] = make_float4(psp[0]*pc0[0].y, psp[1]*pc0[1].y, psp[2]*pc0[2].y, psp[3]*pc0[3].y);
        *(float4*)&As[2 * 1024 + a_base] = make_float4(psp[0]*pc0[0].z, psp[1]*pc0[1].z, psp[2]*pc0[2].z, psp[3]*pc0[3].z);
        *(float4*)&As[3 * 1024 + a_base] = make_float4(psp[0]*pc0[0].w, psp[1]*pc0[1].w, psp[2]*pc0[2].w, psp[3]*pc0[3].w);
        *(float4*)&As[4 * 1024 + a_base] = make_float4(psp[0]*pc1[0].x, psp[1]*pc1[1].x, psp[2]*pc1[2].x, psp[3]*pc1[3].x);
        *(float4*)&As[5 * 1024 + a_base] = make_float4(psp[0]*pc1[0].y, psp[1]*pc1[1].y, psp[2]*pc1[2].y, psp[3]*pc1[3].y);
        *(float4*)&As[6 * 1024 + a_base] = make_float4(psp[0]*pc1[0].z, psp[1]*pc1[1].z, psp[2]*pc1[2].z, psp[3]*pc1[3].z);
        *(float4*)&As[7 * 1024 + a_base] = make_float4(psp[0]*pc1[0].w, psp[1]*pc1[1].w, psp[2]*pc1[2].w, psp[3]*pc1[3].w);
        *(float4*)&As[8 * 1024 + a_base] = make_float4(psb[0], psb[1], psb[2], psb[3]);
    };
    auto prodB = [&](uint32_t offB) {
        uint32_t* Bs = (uint32_t*)(smem + offB);
#pragma unroll
        for (int p = 0; p < 2; p++) {
            uint32_t* base = Bs + b_base[p];
#pragma unroll
            for (int g = 0; g < 8; g++)
                *(float2*)&base[g * 1024] = make_float2(0.0f, 0.0f);
            Bsp bs0 = bspline4(px[p][0]);
            Bsp bs1 = bspline4(px[p][1]);
            float w0[4] = { bs0.w0, bs0.w1, bs0.w2, bs0.w3 };
            float w1[4] = { bs1.w0, bs1.w1, bs1.w2, bs1.w3 };
#pragma unroll
            for (int j = 0; j < 4; j++) {
                int g0 = bs0.m - 3 + j;
                if (g0 >= 0 && g0 <= 7) base[g0 * 1024]     = __float_as_uint(w0[j]);
                int g1 = bs1.m - 3 + j;
                if (g1 >= 0 && g1 <= 7) base[g1 * 1024 + 1] = __float_as_uint(w1[j]);
            }
            *(float2*)&base[8 * 1024] = make_float2(silu_f(px[p][0]), silu_f(px[p][1]));
        }
    };
    auto consume = [&](uint32_t offA, uint32_t offB) {
        const float4* As = (const float4*)(smem + offA);
        const float2* Bs = (const float2*)(smem + offB);
#pragma unroll
        for (int ks = 0; ks < NKS; ks++) {
            uint32_t af[4][4], bf[4][2];
#pragma unroll
            for (int mi = 0; mi < 4; mi++) {
                float4 v = As[(ks * 8 + wm * 4 + mi) * 32 + lane];
                af[mi][0] = __float_as_uint(v.x); af[mi][1] = __float_as_uint(v.y);
                af[mi][2] = __float_as_uint(v.z); af[mi][3] = __float_as_uint(v.w);
            }
#pragma unroll
            for (int ni = 0; ni < 4; ni++) {
                float2 v = Bs[(ks * 16 + wn * 4 + ni) * 32 + lane];
                bf[ni][0] = __float_as_uint(v.x); bf[ni][1] = __float_as_uint(v.y);
            }
#pragma unroll
            for (int mi = 0; mi < 4; mi++)
#pragma unroll
                for (int ni = 0; ni < 4; ni++) mma8(acc[mi][ni], af[mi], bf[ni]);
        }
    };

    // --- pipeline (R5 order): ldg(t+1); consume(t); sts(t+1); sync ---
    ldgA(i0); ldgB(i0);
    stsA(SM_A0); prodB(SM_B0);
    __syncthreads();

    for (int t = 0; t < NCH; t++) {
        const uint32_t offA = (t & 1) ? SM_A1 : SM_A0;
        const uint32_t offB = (t & 1) ? SM_B1 : SM_B0;
        const uint32_t nfA  = (t & 1) ? SM_A0 : SM_A1;
        const uint32_t nfB  = (t & 1) ? SM_B0 : SM_B1;
        if (t + 1 < NCH) { ldgA(i0 + (t + 1) * 8); ldgB(i0 + (t + 1) * 8); }
        consume(offA, offB);
        if (t + 1 < NCH) { stsA(nfA); prodB(nfB); }
        __syncthreads();
    }

    // --- writeout: transpose through smem, coalesced float4 partial stores ---
    {
        float* S = (float*)(smem + SM_A0);          // [128 b][pitch SP]
        const int r = lane >> 2, c = lane & 3;
#pragma unroll
        for (int mi = 0; mi < 4; mi++)
#pragma unroll
            for (int ni = 0; ni < 4; ni++)
#pragma unroll
                for (int w = 0; w < 4; w++) {
                    int o_l = (wm * 4 + mi) * 16 + r + 8 * (w >> 1);
                    int b_l = (wn * 4 + ni) * 8 + 2 * c + (w & 1);
                    S[b_l * SP + o_l] = acc[mi][ni][w];
                }
        __syncthreads();
        float* Y = g_Y1p + split * (B_ * H_);
#pragma unroll
        for (int p = 0; p < 16; p++) {
            int idx = tid + 256 * p;
            int bb = idx >> 5, o4 = idx & 31;
            float4 v = *(float4*)&S[bb * SP + o4 * 4];
            *(float4*)&Y[bb * H_ + o0 + o4 * 4] = v;
        }
    }
}

// ---------------------------------------------------------------------------
// K3a: split reduction, 256 CTAs (validated round 5).
// ---------------------------------------------------------------------------
__global__ void __launch_bounds__(256) k3a_reduce() {
    __shared__ float4 sred[8][32];
    const int t = threadIdx.x, c = blockIdx.x;
    const int lane = t & 31, w = t >> 5;
    const int out = c * 32 + lane;
    const int b = out >> 6, o4 = out & 63;

    const float4* P = (const float4*)g_Y1p;
    float4 acc = make_float4(0.f, 0.f, 0.f, 0.f);
#pragma unroll
    for (int k = 0; k < 8; k++) {
        int s = w * 8 + k;
        float4 v = P[(s * B_ + b) * (H_ / 4) + o4];
        acc.x += v.x; acc.y += v.y; acc.z += v.z; acc.w += v.w;
    }
    sred[w][lane] = acc;
    __syncthreads();
    if (t < 32) {
        float4 a = sred[0][t];
#pragma unroll
        for (int j = 1; j < 8; j++) {
            float4 v = sred[j][t];
            a.x += v.x; a.y += v.y; a.z += v.z; a.w += v.w;
        }
        ((float4*)g_Y1)[c * 32 + t] = a;
    }
}

// ---------------------------------------------------------------------------
// K3b: layer 2, shfl reduction (validated round 5).
// ---------------------------------------------------------------------------
__global__ void __launch_bounds__(256) k3b_layer2(const float* __restrict__ coef2,
                                                 const float* __restrict__ sb2,
                                                 const float* __restrict__ ssp2,
                                                 float* __restrict__ out) {
    const int b = blockIdx.x;
    const int t = threadIdx.x;
    const int lane = t & 31, w = t >> 5;

    float h = selu_f(g_Y1[b * H_ + t]);
    Bsp bs = bspline4(h);
    float f0 = silu_f(h);
    float fb[8];
#pragma unroll
    for (int g = 0; g < 8; g++) fb[g] = bsp_at(bs, g);

    __shared__ float red[OUT_ * 8];
    float val[OUT_];
#pragma unroll
    for (int o = 0; o < OUT_; o++) {
        int e = o * H_ + t;
        float4 c0 = ((const float4*)coef2)[e * 2];
        float4 c1 = ((const float4*)coef2)[e * 2 + 1];
        float sp = ssp2[e];
        float spline = fb[0] * c0.x + fb[1] * c0.y + fb[2] * c0.z + fb[3] * c0.w
                     + fb[4] * c1.x + fb[5] * c1.y + fb[6] * c1.z + fb[7] * c1.w;
        val[o] = sb2[e] * f0 + sp * spline;
    }
#pragma unroll
    for (int o = 0; o < OUT_; o++) {
#pragma unroll
        for (int off = 16; off > 0; off >>= 1)
            val[o] += __shfl_down_sync(0xFFFFFFFFu, val[o], off);
    }
    if (lane == 0) {
#pragma unroll
        for (int o = 0; o < OUT_; o++) red[o * 8 + w] = val[o];
    }
    __syncthreads();
    if (t < OUT_) {
        float s = 0.0f;
#pragma unroll
        for (int j = 0; j < 8; j++) s += red[t * 8 + j];
        out[b * OUT_ + t] = s;
    }
}

// ---------------------------------------------------------------------------
extern "C" void kernel_launch(void* const* d_in, const int* in_sizes, int n_in,
                              void* d_out, int out_size) {
    const float* x     = (const float*)d_in[0];
    const float* coef1 = (const float*)d_in[1];
    const float* sb1   = (const float*)d_in[2];
    const float* ssp1  = (const float*)d_in[3];
    const float* coef2 = (const float*)d_in[4];
    const float* sb2   = (const float*)d_in[5];
    const float* ssp2  = (const float*)d_in[6];
    float* out = (float*)d_out;

    cudaFuncSetAttribute(k2_mma, cudaFuncAttributeMaxDynamicSharedMemorySize, SMEM_TOTAL);
    k2_mma<<<dim3(2, KSPLIT), 256, SMEM_TOTAL>>>(x, coef1, sb1, ssp1);
    k3a_reduce<<<(B_ * H_) / (32 * 4), 256>>>();
    k3b_layer2<<<B_, 256>>>(coef2, sb2, ssp2, out);
}